// round 11
// baseline (speedup 1.0000x reference)
#include <cuda_runtime.h>

// RotationPerturbationLayer as zero-padded bilinear rotation resample.
// theta: [B=4] deg, image: [C=3, H=80, W=80] fp32 -> out [B, C, H, W].
//
// R9: revert to best-measured geometry (R2: 80 blocks x 320 threads,
// 1 pixel/thread = 25600 threads, 10 warps/SM on 80 SMs — latency hiding
// beats instruction-count reduction here), keeping only occupancy-neutral
// body shaves: per-axis masked weights + hoisted channel base pointers.

#define H 80
#define W 80
#define C 3
#define B 4
#define NPIX (H * W)

__global__ __launch_bounds__(320)
void rot_bilinear_kernel(const float* __restrict__ theta,
                         const float* __restrict__ image,
                         float* __restrict__ out) {
    const int x = threadIdx.x;                       // 0..79
    const int y = blockIdx.x * 4 + threadIdx.y;      // 0..79
    const int b = blockIdx.y;                        // 0..3

    const float cx = (W - 1) * 0.5f;   // 39.5
    const float cy = (H - 1) * 0.5f;

    // broadcast L2 load; all threads in block share b
    float th = theta[b] * 0.017453292519943295f;
    float s, c;
    __sincosf(th, &s, &c);

    float x_rel = (float)x - cx;
    float y_rel = (float)y - cy;

    // rotation matrix [[cos, sin], [-sin, cos]]
    float src_x = fmaf(c,  x_rel, fmaf(s, y_rel, cx));
    float src_y = fmaf(-s, x_rel, fmaf(c, y_rel, cy));

    float fx0 = floorf(src_x);
    float fy0 = floorf(src_y);
    int x0 = (int)fx0;
    int y0 = (int)fy0;
    int x1 = x0 + 1;
    int y1 = y0 + 1;
    float ax = src_x - fx0;
    float ay = src_y - fy0;

    // per-axis masked tent weights: product is 0 whenever either axis is OOB
    // (exact zero-padding semantics of the reference's dense tent matmul)
    float wx0 = ((x0 >= 0) & (x0 < W)) ? (1.0f - ax) : 0.0f;
    float wx1 = ((x1 >= 0) & (x1 < W)) ? ax          : 0.0f;
    float wy0 = ((y0 >= 0) & (y0 < H)) ? (1.0f - ay) : 0.0f;
    float wy1 = ((y1 >= 0) & (y1 < H)) ? ay          : 0.0f;

    float m00 = wy0 * wx0;
    float m10 = wy0 * wx1;
    float m01 = wy1 * wx0;
    float m11 = wy1 * wx1;

    // clamp indices so addresses are valid (weight already zeroed)
    int xc0 = min(max(x0, 0), W - 1);
    int xc1 = min(max(x1, 0), W - 1);
    int yc0 = min(max(y0, 0), H - 1);
    int yc1 = min(max(y1, 0), H - 1);

    int i00 = yc0 * W + xc0;
    int i10 = yc0 * W + xc1;
    int i01 = yc1 * W + xc0;
    int i11 = yc1 * W + xc1;

    const float* c0 = image;
    const float* c1 = image + NPIX;
    const float* c2 = image + 2 * NPIX;

    // 12 independent gathers, batched: one exposed L2 latency per warp
    float v00_0 = __ldg(c0 + i00);
    float v10_0 = __ldg(c0 + i10);
    float v01_0 = __ldg(c0 + i01);
    float v11_0 = __ldg(c0 + i11);
    float v00_1 = __ldg(c1 + i00);
    float v10_1 = __ldg(c1 + i10);
    float v01_1 = __ldg(c1 + i01);
    float v11_1 = __ldg(c1 + i11);
    float v00_2 = __ldg(c2 + i00);
    float v10_2 = __ldg(c2 + i10);
    float v01_2 = __ldg(c2 + i01);
    float v11_2 = __ldg(c2 + i11);

    int pix = y * W + x;
    float* ob = out + (size_t)b * C * NPIX + pix;

    float r0 = m00 * v00_0;
    r0 = fmaf(m10, v10_0, r0);
    r0 = fmaf(m01, v01_0, r0);
    r0 = fmaf(m11, v11_0, r0);

    float r1 = m00 * v00_1;
    r1 = fmaf(m10, v10_1, r1);
    r1 = fmaf(m01, v01_1, r1);
    r1 = fmaf(m11, v11_1, r1);

    float r2 = m00 * v00_2;
    r2 = fmaf(m10, v10_2, r2);
    r2 = fmaf(m01, v01_2, r2);
    r2 = fmaf(m11, v11_2, r2);

    ob[0 * NPIX] = r0;
    ob[1 * NPIX] = r1;
    ob[2 * NPIX] = r2;
}

extern "C" void kernel_launch(void* const* d_in, const int* in_sizes, int n_in,
                              void* d_out, int out_size) {
    const float* theta = (const float*)d_in[0];
    const float* image = (const float*)d_in[1];
    if (n_in >= 2 && in_sizes[0] != 4 && in_sizes[1] == 4) {
        theta = (const float*)d_in[1];
        image = (const float*)d_in[0];
    }
    float* out = (float*)d_out;

    dim3 block(80, 4, 1);        // 320 threads, 1 px/thread
    dim3 grid(H / 4, B, 1);      // 20 x 4 = 80 blocks, exactly one wave
    rot_bilinear_kernel<<<grid, block>>>(theta, image, out);
}

// round 13
// speedup vs baseline: 1.1082x; 1.1082x over previous
#include <cuda_runtime.h>

// RotationPerturbationLayer as zero-padded bilinear rotation resample.
// theta: [B=4] deg, image: [C=3, H=80, W=80] fp32 -> out [B, C, H, W].
//
// R12 = best-measured body (R2: 80 blocks x 320 threads, 1 px/thread,
// bool-AND masks -> kernel 4.42us) + two chain shaves:
//   - truncation-floor (src coords biased by +64, always positive)
//   - theta load issued first to overlap L2 latency with index setup

#define H 80
#define W 80
#define C 3
#define B 4
#define NPIX (H * W)

__global__ __launch_bounds__(320)
void rot_bilinear_kernel(const float* __restrict__ theta,
                         const float* __restrict__ image,
                         float* __restrict__ out) {
    const int b = blockIdx.y;                        // 0..3
    // issue the broadcast load immediately; latency overlaps setup below
    float thdeg = __ldg(theta + b);

    const int x = threadIdx.x;                       // 0..79
    const int y = blockIdx.x * 4 + threadIdx.y;      // 0..79

    const float cx = (W - 1) * 0.5f;   // 39.5
    const float cy = (H - 1) * 0.5f;

    float x_rel = (float)x - cx;
    float y_rel = (float)y - cy;

    float th = thdeg * 0.017453292519943295f;
    float s, c;
    __sincosf(th, &s, &c);

    // rotation matrix [[cos, sin], [-sin, cos]]
    float src_x = fmaf(c,  x_rel, fmaf(s, y_rel, cx));
    float src_y = fmaf(-s, x_rel, fmaf(c, y_rel, cy));

    // truncation-floor: src_* in [-56.1, 95.6+], so +64 keeps it positive;
    // (int) truncation == floor for non-negative values. x0 exact in fp32.
    int x0 = (int)(src_x + 64.0f) - 64;
    int y0 = (int)(src_y + 64.0f) - 64;
    int x1 = x0 + 1;
    int y1 = y0 + 1;
    float ax = src_x - (float)x0;
    float ay = src_y - (float)y0;

    // tent weights (R2 formulation: full weights, bool-AND zero-pad masks)
    float w00 = (1.0f - ax) * (1.0f - ay);
    float w10 = ax * (1.0f - ay);
    float w01 = (1.0f - ax) * ay;
    float w11 = ax * ay;

    bool x0ok = (x0 >= 0) & (x0 < W);
    bool x1ok = (x1 >= 0) & (x1 < W);
    bool y0ok = (y0 >= 0) & (y0 < H);
    bool y1ok = (y1 >= 0) & (y1 < H);

    float m00 = (x0ok & y0ok) ? w00 : 0.0f;
    float m10 = (x1ok & y0ok) ? w10 : 0.0f;
    float m01 = (x0ok & y1ok) ? w01 : 0.0f;
    float m11 = (x1ok & y1ok) ? w11 : 0.0f;

    // clamp indices so addresses are valid (weight already zeroed)
    int xc0 = min(max(x0, 0), W - 1);
    int xc1 = min(max(x1, 0), W - 1);
    int yc0 = min(max(y0, 0), H - 1);
    int yc1 = min(max(y1, 0), H - 1);

    int i00 = yc0 * W + xc0;
    int i10 = yc0 * W + xc1;
    int i01 = yc1 * W + xc0;
    int i11 = yc1 * W + xc1;

    const float* c0 = image;
    const float* c1 = image + NPIX;
    const float* c2 = image + 2 * NPIX;

    // 12 independent gathers, batched: one exposed L2 latency per warp
    float v00_0 = __ldg(c0 + i00);
    float v10_0 = __ldg(c0 + i10);
    float v01_0 = __ldg(c0 + i01);
    float v11_0 = __ldg(c0 + i11);
    float v00_1 = __ldg(c1 + i00);
    float v10_1 = __ldg(c1 + i10);
    float v01_1 = __ldg(c1 + i01);
    float v11_1 = __ldg(c1 + i11);
    float v00_2 = __ldg(c2 + i00);
    float v10_2 = __ldg(c2 + i10);
    float v01_2 = __ldg(c2 + i01);
    float v11_2 = __ldg(c2 + i11);

    int pix = y * W + x;
    float* ob = out + (size_t)b * C * NPIX + pix;

    float r0 = m00 * v00_0;
    r0 = fmaf(m10, v10_0, r0);
    r0 = fmaf(m01, v01_0, r0);
    r0 = fmaf(m11, v11_0, r0);

    float r1 = m00 * v00_1;
    r1 = fmaf(m10, v10_1, r1);
    r1 = fmaf(m01, v01_1, r1);
    r1 = fmaf(m11, v11_1, r1);

    float r2 = m00 * v00_2;
    r2 = fmaf(m10, v10_2, r2);
    r2 = fmaf(m01, v01_2, r2);
    r2 = fmaf(m11, v11_2, r2);

    ob[0 * NPIX] = r0;
    ob[1 * NPIX] = r1;
    ob[2 * NPIX] = r2;
}

extern "C" void kernel_launch(void* const* d_in, const int* in_sizes, int n_in,
                              void* d_out, int out_size) {
    const float* theta = (const float*)d_in[0];
    const float* image = (const float*)d_in[1];
    if (n_in >= 2 && in_sizes[0] != 4 && in_sizes[1] == 4) {
        theta = (const float*)d_in[1];
        image = (const float*)d_in[0];
    }
    float* out = (float*)d_out;

    dim3 block(80, 4, 1);        // 320 threads, 1 px/thread
    dim3 grid(H / 4, B, 1);      // 20 x 4 = 80 blocks, exactly one wave
    rot_bilinear_kernel<<<grid, block>>>(theta, image, out);
}